// round 12
// baseline (speedup 1.0000x reference)
#include <cuda_runtime.h>

#define NN 100000
#define EE 1250000
#define DD 64
#define LL 5
#define GG 128
#define TT 37
#define DE 7
#define NCH 196          // ceil(NN/512)

#define SC_BLOCKS 592                     // 148 SMs x 4 resident blocks
#define SC_W (SC_BLOCKS * 8)              // warps in scatter grid
#define EPW ((EE + SC_W - 1) / SC_W)      // edges per warp chunk

typedef unsigned long long ull;

__device__ __forceinline__ ull pack_dup(float a) {
    ull r;
    unsigned u = __float_as_uint(a);
    asm("mov.b64 %0, {%1,%2};" : "=l"(r) : "r"(u), "r"(u));
    return r;
}
__device__ __forceinline__ void unpack2(ull v, float& lo, float& hi) {
    unsigned a, b;
    asm("mov.b64 {%0,%1}, %2;" : "=r"(a), "=r"(b) : "l"(v));
    lo = __uint_as_float(a);
    hi = __uint_as_float(b);
}
#define FMA2(d, a, b, c) \
    asm("fma.rn.f32x2 %0, %1, %2, %3;" : "=l"(d) : "l"(a), "l"(b), "l"(c))
#define ADD2(d, a, b) \
    asm("add.rn.f32x2 %0, %1, %2;" : "=l"(d) : "l"(a), "l"(b))

// ---------------- device scratch ----------------
__device__ float d_hbuf[LL * NN * DD];    // per-layer node embeddings
__device__ float d_agg[NN * DD];
__device__ int2  d_edgeP[EE];             // {src,dst} sorted by src
__device__ float d_eattrP[EE * 8];        // edge attrs permuted to src order
__device__ int   d_deg[NN];               // out-degree
__device__ int   d_off[NN];
__device__ int   d_cur[NN];
__device__ int   d_chtot[256];
__device__ int   d_batch32[NN];
__device__ float d_gpool[GG * LL * DD];
__device__ int   d_flags[2];

// ---------------- zero + dtype detection (merged) -------------------------
__global__ void init_kernel(const unsigned* __restrict__ ei,
                            const unsigned* __restrict__ batch) {
    int i = blockIdx.x * blockDim.x + threadIdx.x;
    if (i < NN) d_deg[i] = 0;
    if (i < GG * LL * DD) d_gpool[i] = 0.0f;
    if (i == 0) {
        int f = 1;
        for (int k = 0; k < 64; k++)
            if (ei[1000001 + 2 * k] != 0u) { f = 0; break; }
        d_flags[0] = f;
        int fb = 1;
        for (int k = 0; k < 64; k++)
            if (batch[(NN - 1) - 2 * k] != 0u) { fb = 0; break; }
        d_flags[1] = fb;
    }
}

// ---------------- histogram + batch convert -------------------------------
__global__ void convert_kernel(const void* __restrict__ ei,
                               const void* __restrict__ batch) {
    int i = blockIdx.x * blockDim.x + threadIdx.x;
    int e64 = d_flags[0];
    int b64 = d_flags[1];
    if (i < EE) {
        int s;
        if (e64) s = (int)((const long long*)ei)[i];
        else     s = ((const int*)ei)[i];
        atomicAdd(&d_deg[s], 1);
    }
    if (i < NN) {
        if (b64) d_batch32[i] = (int)((const long long*)batch)[i];
        else     d_batch32[i] = ((const int*)batch)[i];
    }
}

// ---------------- scans ----------------
__global__ void scan1_kernel() {
    __shared__ int wsum[16];
    int t = threadIdx.x;
    int lane = t & 31, w = t >> 5;
    int g = blockIdx.x * 512 + t;
    int v = (g < NN) ? d_deg[g] : 0;
    int s = v;
#pragma unroll
    for (int off = 1; off < 32; off <<= 1) {
        int x = __shfl_up_sync(0xffffffffu, s, off);
        if (lane >= off) s += x;
    }
    if (lane == 31) wsum[w] = s;
    __syncthreads();
    if (w == 0) {
        int ws = (lane < 16) ? wsum[lane] : 0;
#pragma unroll
        for (int off = 1; off < 16; off <<= 1) {
            int x = __shfl_up_sync(0xffffffffu, ws, off);
            if (lane >= off) ws += x;
        }
        if (lane < 16) wsum[lane] = ws;
    }
    __syncthreads();
    int woff = (w > 0) ? wsum[w - 1] : 0;
    if (g < NN) d_off[g] = woff + s - v;    // exclusive
    if (t == 511) d_chtot[blockIdx.x] = wsum[15];
}

// scan3 computes its own inter-chunk prefix (folds old scan2 in)
__global__ void scan3_kernel() {
    __shared__ int base_sh;
    int t = threadIdx.x;
    int bid = blockIdx.x;
    if (t < 32) {
        int s = 0;
        for (int i = t; i < bid; i += 32) s += d_chtot[i];
#pragma unroll
        for (int off = 16; off; off >>= 1)
            s += __shfl_down_sync(0xffffffffu, s, off);
        if (t == 0) base_sh = s;
    }
    __syncthreads();
    int g = bid * 512 + t;
    if (g < NN) {
        int o = d_off[g] + base_sh;
        d_off[g] = o;
        d_cur[g] = o;
    }
}

// ---------------- permute edges into src-sorted order ---------------------
__global__ void csrscat_kernel(const void* __restrict__ ei,
                               const float* __restrict__ eattr) {
    int e = blockIdx.x * blockDim.x + threadIdx.x;
    if (e >= EE) return;
    int e64 = d_flags[0];
    int s, d;
    if (e64) {
        const long long* p = (const long long*)ei;
        s = (int)p[e]; d = (int)p[e + EE];
    } else {
        const int* p = (const int*)ei;
        s = p[e]; d = p[e + EE];
    }
    int pos = atomicAdd(&d_cur[s], 1);
    d_edgeP[pos] = make_int2(s, d);
    const float* ea = eattr + (size_t)e * DE;
    float4 v0 = make_float4(ea[0], ea[1], ea[2], ea[3]);
    float4 v1 = make_float4(ea[4], ea[5], ea[6], 0.0f);
    float4* p4 = (float4*)(d_eattrP + (size_t)pos * 8);
    p4[0] = v0; p4[1] = v1;
}

// ---------------- agg = (1 + eps[0]) * x  (layer 0 only) ------------------
__global__ void pre_kernel(const float* __restrict__ hprev,
                           const float* __restrict__ eps) {
    int i = blockIdx.x * blockDim.x + threadIdx.x;
    const int n4 = NN * DD / 4;
    if (i >= n4) return;
    float s = 1.0f + __ldg(eps);
    float4 v = ((const float4*)hprev)[i];
    v.x *= s; v.y *= s; v.z *= s; v.w *= s;
    ((float4*)d_agg)[i] = v;
}

// ---------------- scatter: agg[dst] += relu(h[src] + edge_emb) ------------
// FULL warp per edge, 2 cols/lane, f32x2 math; register-lean (no spills).
// Src-sorted contiguous chunks; h[src] cached in registers across runs.
__global__ void __launch_bounds__(256, 4) scatter_kernel(
        const float* __restrict__ hprev,
        const float* __restrict__ We,
        const float* __restrict__ be) {
    int lane = threadIdx.x & 31;
    int c = lane * 2;

    ull w[7];
#pragma unroll
    for (int k = 0; k < 7; k++)
        w[k] = *(const ull*)(We + k * DD + c);
    ull b2 = *(const ull*)(be + c);

    int wid = (blockIdx.x * blockDim.x + threadIdx.x) >> 5;
    long long e0 = (long long)wid * EPW;
    long long e1 = e0 + EPW;
    if (e1 > EE) e1 = EE;

    int sprev = -1;
    ull h2 = 0;

#pragma unroll 2
    for (long long e = e0; e < e1; e++) {
        int2 sd = __ldg(&d_edgeP[e]);
        float4 a0 = __ldg((const float4*)(d_eattrP + (size_t)e * 8));
        float4 a1 = __ldg((const float4*)(d_eattrP + (size_t)e * 8 + 4));
        if (sd.x != sprev) {
            h2 = __ldg((const ull*)(hprev + (size_t)sd.x * DD + c));
            sprev = sd.x;
        }

        ull m = b2;
        FMA2(m, pack_dup(a0.x), w[0], m);
        FMA2(m, pack_dup(a0.y), w[1], m);
        FMA2(m, pack_dup(a0.z), w[2], m);
        FMA2(m, pack_dup(a0.w), w[3], m);
        FMA2(m, pack_dup(a1.x), w[4], m);
        FMA2(m, pack_dup(a1.y), w[5], m);
        FMA2(m, pack_dup(a1.z), w[6], m);
        ADD2(m, m, h2);

        float f0, f1;
        unpack2(m, f0, f1);
        f0 = fmaxf(f0, 0.0f);
        f1 = fmaxf(f1, 0.0f);

        float* ap = d_agg + (size_t)sd.y * DD + c;
        asm volatile("red.global.add.v2.f32 [%0], {%1,%2};"
                     :: "l"(ap), "f"(f0), "f"(f1)
                     : "memory");
    }
}

// ---------------- MLP + fused pool (scalar R10 version) -------------------
// 512 threads, 128 nodes/block. h_out = relu(agg @ W + b);
// agg_next = s*h_out; gpool[batch] += h_out (run-merged REDs).
__global__ void __launch_bounds__(512) mlp_kernel(
        const float* __restrict__ W,
        const float* __restrict__ b,
        float* __restrict__ hout,
        const float* __restrict__ eps, int l) {
    __shared__ float Ws[DD * DD];     // 16 KB
    __shared__ float bs[DD];
    __shared__ float u[128 * DD];     // 32 KB

    int t = threadIdx.x;
    for (int i = t; i < DD * DD / 4; i += 512)
        ((float4*)Ws)[i] = ((const float4*)W)[i];
    if (t < DD) bs[t] = b[t];

    int node0 = blockIdx.x * 128;
    for (int i = t; i < 128 * 16; i += 512) {
        int node = node0 + (i >> 4);
        float4 v = (node < NN)
            ? ((const float4*)(d_agg + (size_t)node * DD))[i & 15]
            : make_float4(0.f, 0.f, 0.f, 0.f);
        ((float4*)u)[i] = v;
    }
    __syncthreads();

    float snext = (l < LL - 1) ? (1.0f + __ldg(eps + l + 1)) : 0.0f;

    int c4 = (t & 15) * 4;
    int n4 = (t >> 4) * 4;           // 0..124

    float acc[4][4];
#pragma unroll
    for (int ni = 0; ni < 4; ni++) {
        acc[ni][0] = bs[c4 + 0];
        acc[ni][1] = bs[c4 + 1];
        acc[ni][2] = bs[c4 + 2];
        acc[ni][3] = bs[c4 + 3];
    }

#pragma unroll 8
    for (int k = 0; k < DD; k++) {
        float4 w = *(const float4*)(Ws + k * DD + c4);
#pragma unroll
        for (int ni = 0; ni < 4; ni++) {
            float uv = u[(n4 + ni) * DD + k];
            acc[ni][0] = fmaf(uv, w.x, acc[ni][0]);
            acc[ni][1] = fmaf(uv, w.y, acc[ni][1]);
            acc[ni][2] = fmaf(uv, w.z, acc[ni][2]);
            acc[ni][3] = fmaf(uv, w.w, acc[ni][3]);
        }
    }

    // epilogue: write h_out (+scaled agg), pool with run-merged REDs
    float p0 = 0.f, p1 = 0.f, p2 = 0.f, p3 = 0.f;
    int gcur = -1;
#pragma unroll
    for (int ni = 0; ni < 4; ni++) {
        int node = node0 + n4 + ni;
        if (node < NN) {
            float o0 = fmaxf(acc[ni][0], 0.0f);
            float o1 = fmaxf(acc[ni][1], 0.0f);
            float o2 = fmaxf(acc[ni][2], 0.0f);
            float o3 = fmaxf(acc[ni][3], 0.0f);
            if (l < LL - 1) {
                // next-layer scatter reads h; also prime agg for next layer
                *(float4*)(hout + (size_t)node * DD + c4) =
                    make_float4(o0, o1, o2, o3);
                *(float4*)(d_agg + (size_t)node * DD + c4) =
                    make_float4(snext * o0, snext * o1, snext * o2, snext * o3);
            }
            int g = d_batch32[node];
            if (g != gcur) {
                if (gcur >= 0) {
                    float* gp = d_gpool + (size_t)gcur * (LL * DD) + l * DD + c4;
                    asm volatile("red.global.add.v4.f32 [%0], {%1,%2,%3,%4};"
                                 :: "l"(gp), "f"(p0), "f"(p1), "f"(p2), "f"(p3)
                                 : "memory");
                }
                gcur = g;
                p0 = p1 = p2 = p3 = 0.f;
            }
            p0 += o0; p1 += o1; p2 += o2; p3 += o3;
        }
    }
    if (gcur >= 0) {
        float* gp = d_gpool + (size_t)gcur * (LL * DD) + l * DD + c4;
        asm volatile("red.global.add.v4.f32 [%0], {%1,%2,%3,%4};"
                     :: "l"(gp), "f"(p0), "f"(p1), "f"(p2), "f"(p3)
                     : "memory");
    }
}

// ---------------- predictor (divides pooled sum by count) ------------------
__device__ __forceinline__ int lower_bound_i(const int* a, int n, int v) {
    int lo = 0, hi = n;
    while (lo < hi) {
        int m = (lo + hi) >> 1;
        if (a[m] < v) lo = m + 1; else hi = m;
    }
    return lo;
}

__global__ void pred_kernel(const float* __restrict__ Wp,
                            const float* __restrict__ bp,
                            float* __restrict__ out) {
    int i = blockIdx.x * blockDim.x + threadIdx.x;
    if (i >= GG * TT) return;
    int g = i / TT, t = i % TT;
    int start = lower_bound_i(d_batch32, NN, g);
    int end   = lower_bound_i(d_batch32, NN, g + 1);
    int cnt = end - start;
    float inv = 1.0f / (float)(cnt > 0 ? cnt : 1);
    const float* gp = d_gpool + g * (LL * DD);
    float s = 0.0f;
    for (int c = 0; c < LL * DD; c++)
        s = fmaf(gp[c], __ldg(Wp + c * TT + t), s);
    out[i] = fmaf(inv, s, __ldg(bp + t));
}

// ---------------- launch -------------------------------------------------
extern "C" void kernel_launch(void* const* d_in, const int* in_sizes, int n_in,
                              void* d_out, int out_size) {
    const float* x     = (const float*)d_in[0];
    const void*  ei    = d_in[1];
    const float* eattr = (const float*)d_in[2];
    const void*  batch = d_in[3];
    const float* We    = (const float*)d_in[4];
    const float* be    = (const float*)d_in[5];
    const float* eps   = (const float*)d_in[6];
    const float* Wm    = (const float*)d_in[7];
    const float* bm    = (const float*)d_in[8];
    const float* Wp    = (const float*)d_in[9];
    const float* bp    = (const float*)d_in[10];
    float* out = (float*)d_out;

    init_kernel<<<(NN + 255) / 256, 256>>>((const unsigned*)ei,
                                           (const unsigned*)batch);
    convert_kernel<<<(EE + 255) / 256, 256>>>(ei, batch);
    scan1_kernel<<<NCH, 512>>>();
    scan3_kernel<<<NCH, 512>>>();
    csrscat_kernel<<<(EE + 255) / 256, 256>>>(ei, eattr);

    float* hbuf = nullptr;
    cudaGetSymbolAddress((void**)&hbuf, d_hbuf);

    pre_kernel<<<(NN * DD / 4 + 255) / 256, 256>>>(x, eps);

    const float* hprev = x;
    for (int l = 0; l < LL; l++) {
        scatter_kernel<<<SC_BLOCKS, 256>>>(hprev, We, be);
        float* hout = hbuf + (size_t)l * NN * DD;
        mlp_kernel<<<(NN + 127) / 128, 512>>>(Wm + l * DD * DD, bm + l * DD,
                                              hout, eps, l);
        hprev = hout;
    }

    pred_kernel<<<(GG * TT + 255) / 256, 256>>>(Wp, bp, out);
}

// round 14
// speedup vs baseline: 1.1044x; 1.1044x over previous
#include <cuda_runtime.h>

#define NN 100000
#define EE 1250000
#define DD 64
#define LL 5
#define GG 128
#define TT 37
#define DE 7
#define NCH 196          // ceil(NN/512)

#define SC_BLOCKS 592                     // 148 SMs x 4 resident blocks
#define SC_HW (SC_BLOCKS * 16)            // half-warps in scatter grid
#define EPH ((EE + SC_HW - 1) / SC_HW)    // edges per half-warp chunk

// ---------------- device scratch ----------------
__device__ float d_hbuf[LL * NN * DD];    // per-layer node embeddings
__device__ float d_agg[NN * DD];
__device__ int2  d_edgeP[EE];             // {src,dst} sorted by src
__device__ float d_eattrP[EE * 8];        // edge attrs permuted to src order
__device__ int   d_deg[NN];               // out-degree
__device__ int   d_off[NN];
__device__ int   d_cur[NN];
__device__ int   d_chtot[256];
__device__ int   d_batch32[NN];
__device__ float d_gpool[GG * LL * DD];
__device__ int   d_flags[2];

// ---------------- zero + dtype detection (merged) -------------------------
__global__ void init_kernel(const unsigned* __restrict__ ei,
                            const unsigned* __restrict__ batch) {
    int i = blockIdx.x * blockDim.x + threadIdx.x;
    if (i < NN) d_deg[i] = 0;
    if (i < GG * LL * DD) d_gpool[i] = 0.0f;
    if (i == 0) {
        int f = 1;
        for (int k = 0; k < 64; k++)
            if (ei[1000001 + 2 * k] != 0u) { f = 0; break; }
        d_flags[0] = f;
        int fb = 1;
        for (int k = 0; k < 64; k++)
            if (batch[(NN - 1) - 2 * k] != 0u) { fb = 0; break; }
        d_flags[1] = fb;
    }
}

// ---------------- histogram + batch convert -------------------------------
__global__ void convert_kernel(const void* __restrict__ ei,
                               const void* __restrict__ batch) {
    int i = blockIdx.x * blockDim.x + threadIdx.x;
    int e64 = d_flags[0];
    int b64 = d_flags[1];
    if (i < EE) {
        int s;
        if (e64) s = (int)((const long long*)ei)[i];
        else     s = ((const int*)ei)[i];
        atomicAdd(&d_deg[s], 1);
    }
    if (i < NN) {
        if (b64) d_batch32[i] = (int)((const long long*)batch)[i];
        else     d_batch32[i] = ((const int*)batch)[i];
    }
}

// ---------------- scans ----------------
__global__ void scan1_kernel() {
    __shared__ int wsum[16];
    int t = threadIdx.x;
    int lane = t & 31, w = t >> 5;
    int g = blockIdx.x * 512 + t;
    int v = (g < NN) ? d_deg[g] : 0;
    int s = v;
#pragma unroll
    for (int off = 1; off < 32; off <<= 1) {
        int x = __shfl_up_sync(0xffffffffu, s, off);
        if (lane >= off) s += x;
    }
    if (lane == 31) wsum[w] = s;
    __syncthreads();
    if (w == 0) {
        int ws = (lane < 16) ? wsum[lane] : 0;
#pragma unroll
        for (int off = 1; off < 16; off <<= 1) {
            int x = __shfl_up_sync(0xffffffffu, ws, off);
            if (lane >= off) ws += x;
        }
        if (lane < 16) wsum[lane] = ws;
    }
    __syncthreads();
    int woff = (w > 0) ? wsum[w - 1] : 0;
    if (g < NN) d_off[g] = woff + s - v;    // exclusive
    if (t == 511) d_chtot[blockIdx.x] = wsum[15];
}

// scan3 computes its own inter-chunk prefix (scan2 folded in)
__global__ void scan3_kernel() {
    __shared__ int base_sh;
    int t = threadIdx.x;
    int bid = blockIdx.x;
    if (t < 32) {
        int s = 0;
        for (int i = t; i < bid; i += 32) s += d_chtot[i];
#pragma unroll
        for (int off = 16; off; off >>= 1)
            s += __shfl_down_sync(0xffffffffu, s, off);
        if (t == 0) base_sh = s;
    }
    __syncthreads();
    int g = bid * 512 + t;
    if (g < NN) {
        int o = d_off[g] + base_sh;
        d_off[g] = o;
        d_cur[g] = o;
    }
}

// ---------------- permute edges into src-sorted order ---------------------
__global__ void csrscat_kernel(const void* __restrict__ ei,
                               const float* __restrict__ eattr) {
    int e = blockIdx.x * blockDim.x + threadIdx.x;
    if (e >= EE) return;
    int e64 = d_flags[0];
    int s, d;
    if (e64) {
        const long long* p = (const long long*)ei;
        s = (int)p[e]; d = (int)p[e + EE];
    } else {
        const int* p = (const int*)ei;
        s = p[e]; d = p[e + EE];
    }
    int pos = atomicAdd(&d_cur[s], 1);
    d_edgeP[pos] = make_int2(s, d);
    const float* ea = eattr + (size_t)e * DE;
    float4 v0 = make_float4(ea[0], ea[1], ea[2], ea[3]);
    float4 v1 = make_float4(ea[4], ea[5], ea[6], 0.0f);
    float4* p4 = (float4*)(d_eattrP + (size_t)pos * 8);
    p4[0] = v0; p4[1] = v1;
}

// ---------------- agg = (1 + eps[0]) * x  (layer 0 only) ------------------
__global__ void pre_kernel(const float* __restrict__ hprev,
                           const float* __restrict__ eps) {
    int i = blockIdx.x * blockDim.x + threadIdx.x;
    const int n4 = NN * DD / 4;
    if (i >= n4) return;
    float s = 1.0f + __ldg(eps);
    float4 v = ((const float4*)hprev)[i];
    v.x *= s; v.y *= s; v.z *= s; v.w *= s;
    ((float4*)d_agg)[i] = v;
}

// ---------------- scatter: agg[dst] += relu(h[src] + edge_emb) ------------
// Half-warp per edge, src-sorted contiguous chunks; h[src] cached in
// registers across src-runs; scalar FFMA; red.v4 fire-and-forget.
__global__ void __launch_bounds__(256, 4) scatter_kernel(
        const float* __restrict__ hprev,
        const float* __restrict__ We,
        const float* __restrict__ be) {
    int lane = threadIdx.x & 31;
    int c = (lane & 15) * 4;

    float4 w0 = *(const float4*)(We + 0 * DD + c);
    float4 w1 = *(const float4*)(We + 1 * DD + c);
    float4 w2 = *(const float4*)(We + 2 * DD + c);
    float4 w3 = *(const float4*)(We + 3 * DD + c);
    float4 w4 = *(const float4*)(We + 4 * DD + c);
    float4 w5 = *(const float4*)(We + 5 * DD + c);
    float4 w6 = *(const float4*)(We + 6 * DD + c);
    float4 bv = *(const float4*)(be + c);

    int hwid = (blockIdx.x * blockDim.x + threadIdx.x) >> 4;
    long long e0 = (long long)hwid * EPH;
    long long e1 = e0 + EPH;
    if (e1 > EE) e1 = EE;

    int sprev = -1;
    float4 hv = make_float4(0.f, 0.f, 0.f, 0.f);

#pragma unroll 2
    for (long long e = e0; e < e1; e++) {
        int2 sd = __ldg(&d_edgeP[e]);
        float4 a0 = __ldg((const float4*)(d_eattrP + (size_t)e * 8));
        float4 a1 = __ldg((const float4*)(d_eattrP + (size_t)e * 8 + 4));
        if (sd.x != sprev) {
            hv = __ldg((const float4*)(hprev + (size_t)sd.x * DD + c));
            sprev = sd.x;
        }

        float m0 = bv.x, m1 = bv.y, m2 = bv.z, m3 = bv.w;
        m0 = fmaf(a0.x, w0.x, m0); m1 = fmaf(a0.x, w0.y, m1);
        m2 = fmaf(a0.x, w0.z, m2); m3 = fmaf(a0.x, w0.w, m3);
        m0 = fmaf(a0.y, w1.x, m0); m1 = fmaf(a0.y, w1.y, m1);
        m2 = fmaf(a0.y, w1.z, m2); m3 = fmaf(a0.y, w1.w, m3);
        m0 = fmaf(a0.z, w2.x, m0); m1 = fmaf(a0.z, w2.y, m1);
        m2 = fmaf(a0.z, w2.z, m2); m3 = fmaf(a0.z, w2.w, m3);
        m0 = fmaf(a0.w, w3.x, m0); m1 = fmaf(a0.w, w3.y, m1);
        m2 = fmaf(a0.w, w3.z, m2); m3 = fmaf(a0.w, w3.w, m3);
        m0 = fmaf(a1.x, w4.x, m0); m1 = fmaf(a1.x, w4.y, m1);
        m2 = fmaf(a1.x, w4.z, m2); m3 = fmaf(a1.x, w4.w, m3);
        m0 = fmaf(a1.y, w5.x, m0); m1 = fmaf(a1.y, w5.y, m1);
        m2 = fmaf(a1.y, w5.z, m2); m3 = fmaf(a1.y, w5.w, m3);
        m0 = fmaf(a1.z, w6.x, m0); m1 = fmaf(a1.z, w6.y, m1);
        m2 = fmaf(a1.z, w6.z, m2); m3 = fmaf(a1.z, w6.w, m3);

        m0 = fmaxf(m0 + hv.x, 0.0f);
        m1 = fmaxf(m1 + hv.y, 0.0f);
        m2 = fmaxf(m2 + hv.z, 0.0f);
        m3 = fmaxf(m3 + hv.w, 0.0f);

        float* ap = d_agg + (size_t)sd.y * DD + c;
        asm volatile("red.global.add.v4.f32 [%0], {%1,%2,%3,%4};"
                     :: "l"(ap), "f"(m0), "f"(m1), "f"(m2), "f"(m3)
                     : "memory");
    }
}

// ---------------- MLP + fused pool ---------------------------------------
// 512 threads, 128 nodes/block. h_out = relu(agg @ W + b);
// agg_next = s*h_out; gpool[batch] += h_out (run-merged REDs).
// Last layer: h_out is only pooled, never stored.
__global__ void __launch_bounds__(512) mlp_kernel(
        const float* __restrict__ W,
        const float* __restrict__ b,
        float* __restrict__ hout,
        const float* __restrict__ eps, int l) {
    __shared__ float Ws[DD * DD];     // 16 KB
    __shared__ float bs[DD];
    __shared__ float u[128 * DD];     // 32 KB

    int t = threadIdx.x;
    for (int i = t; i < DD * DD / 4; i += 512)
        ((float4*)Ws)[i] = ((const float4*)W)[i];
    if (t < DD) bs[t] = b[t];

    int node0 = blockIdx.x * 128;
    for (int i = t; i < 128 * 16; i += 512) {
        int node = node0 + (i >> 4);
        float4 v = (node < NN)
            ? ((const float4*)(d_agg + (size_t)node * DD))[i & 15]
            : make_float4(0.f, 0.f, 0.f, 0.f);
        ((float4*)u)[i] = v;
    }
    __syncthreads();

    float snext = (l < LL - 1) ? (1.0f + __ldg(eps + l + 1)) : 0.0f;

    int c4 = (t & 15) * 4;
    int n4 = (t >> 4) * 4;           // 0..124

    float acc[4][4];
#pragma unroll
    for (int ni = 0; ni < 4; ni++) {
        acc[ni][0] = bs[c4 + 0];
        acc[ni][1] = bs[c4 + 1];
        acc[ni][2] = bs[c4 + 2];
        acc[ni][3] = bs[c4 + 3];
    }

#pragma unroll 8
    for (int k = 0; k < DD; k++) {
        float4 w = *(const float4*)(Ws + k * DD + c4);
#pragma unroll
        for (int ni = 0; ni < 4; ni++) {
            float uv = u[(n4 + ni) * DD + k];
            acc[ni][0] = fmaf(uv, w.x, acc[ni][0]);
            acc[ni][1] = fmaf(uv, w.y, acc[ni][1]);
            acc[ni][2] = fmaf(uv, w.z, acc[ni][2]);
            acc[ni][3] = fmaf(uv, w.w, acc[ni][3]);
        }
    }

    // epilogue: write h_out (+scaled agg) unless last layer; pool with
    // run-merged REDs
    float p0 = 0.f, p1 = 0.f, p2 = 0.f, p3 = 0.f;
    int gcur = -1;
#pragma unroll
    for (int ni = 0; ni < 4; ni++) {
        int node = node0 + n4 + ni;
        if (node < NN) {
            float o0 = fmaxf(acc[ni][0], 0.0f);
            float o1 = fmaxf(acc[ni][1], 0.0f);
            float o2 = fmaxf(acc[ni][2], 0.0f);
            float o3 = fmaxf(acc[ni][3], 0.0f);
            if (l < LL - 1) {
                *(float4*)(hout + (size_t)node * DD + c4) =
                    make_float4(o0, o1, o2, o3);
                *(float4*)(d_agg + (size_t)node * DD + c4) =
                    make_float4(snext * o0, snext * o1, snext * o2, snext * o3);
            }
            int g = d_batch32[node];
            if (g != gcur) {
                if (gcur >= 0) {
                    float* gp = d_gpool + (size_t)gcur * (LL * DD) + l * DD + c4;
                    asm volatile("red.global.add.v4.f32 [%0], {%1,%2,%3,%4};"
                                 :: "l"(gp), "f"(p0), "f"(p1), "f"(p2), "f"(p3)
                                 : "memory");
                }
                gcur = g;
                p0 = p1 = p2 = p3 = 0.f;
            }
            p0 += o0; p1 += o1; p2 += o2; p3 += o3;
        }
    }
    if (gcur >= 0) {
        float* gp = d_gpool + (size_t)gcur * (LL * DD) + l * DD + c4;
        asm volatile("red.global.add.v4.f32 [%0], {%1,%2,%3,%4};"
                     :: "l"(gp), "f"(p0), "f"(p1), "f"(p2), "f"(p3)
                     : "memory");
    }
}

// ---------------- predictor (divides pooled sum by count) ------------------
__device__ __forceinline__ int lower_bound_i(const int* a, int n, int v) {
    int lo = 0, hi = n;
    while (lo < hi) {
        int m = (lo + hi) >> 1;
        if (a[m] < v) lo = m + 1; else hi = m;
    }
    return lo;
}

__global__ void pred_kernel(const float* __restrict__ Wp,
                            const float* __restrict__ bp,
                            float* __restrict__ out) {
    int i = blockIdx.x * blockDim.x + threadIdx.x;
    if (i >= GG * TT) return;
    int g = i / TT, t = i % TT;
    int start = lower_bound_i(d_batch32, NN, g);
    int end   = lower_bound_i(d_batch32, NN, g + 1);
    int cnt = end - start;
    float inv = 1.0f / (float)(cnt > 0 ? cnt : 1);
    const float* gp = d_gpool + g * (LL * DD);
    float s = 0.0f;
    for (int c = 0; c < LL * DD; c++)
        s = fmaf(gp[c], __ldg(Wp + c * TT + t), s);
    out[i] = fmaf(inv, s, __ldg(bp + t));
}

// ---------------- launch -------------------------------------------------
extern "C" void kernel_launch(void* const* d_in, const int* in_sizes, int n_in,
                              void* d_out, int out_size) {
    const float* x     = (const float*)d_in[0];
    const void*  ei    = d_in[1];
    const float* eattr = (const float*)d_in[2];
    const void*  batch = d_in[3];
    const float* We    = (const float*)d_in[4];
    const float* be    = (const float*)d_in[5];
    const float* eps   = (const float*)d_in[6];
    const float* Wm    = (const float*)d_in[7];
    const float* bm    = (const float*)d_in[8];
    const float* Wp    = (const float*)d_in[9];
    const float* bp    = (const float*)d_in[10];
    float* out = (float*)d_out;

    init_kernel<<<(NN + 255) / 256, 256>>>((const unsigned*)ei,
                                           (const unsigned*)batch);
    convert_kernel<<<(EE + 255) / 256, 256>>>(ei, batch);
    scan1_kernel<<<NCH, 512>>>();
    scan3_kernel<<<NCH, 512>>>();
    csrscat_kernel<<<(EE + 255) / 256, 256>>>(ei, eattr);

    float* hbuf = nullptr;
    cudaGetSymbolAddress((void**)&hbuf, d_hbuf);

    pre_kernel<<<(NN * DD / 4 + 255) / 256, 256>>>(x, eps);

    const float* hprev = x;
    for (int l = 0; l < LL; l++) {
        scatter_kernel<<<SC_BLOCKS, 256>>>(hprev, We, be);
        float* hout = hbuf + (size_t)l * NN * DD;
        mlp_kernel<<<(NN + 127) / 128, 512>>>(Wm + l * DD * DD, bm + l * DD,
                                              hout, eps, l);
        hprev = hout;
    }

    pred_kernel<<<(GG * TT + 255) / 256, 256>>>(Wp, bp, out);
}